// round 1
// baseline (speedup 1.0000x reference)
#include <cuda_runtime.h>
#include <math.h>

#define N_NODES 50000
#define N_EDGES 800000
#define HID     96
#define BM      128
#define XS_STRIDE 97   // pad to avoid bank conflicts on LDS/STS

// Scratch (device-global: no allocation allowed)
__device__ float g_h[N_NODES * HID];     // gelu(x @ W_pre + b_pre)
__device__ float g_aggr[N_NODES * HID];  // segment_sum of h[src]*bases by dst
__device__ float g_x[N_NODES * HID];     // x_feat + aggr (residual-1 output)
__device__ float g_t[N_NODES * HID];     // gelu(x @ W1 + b1)

__device__ __forceinline__ float gelu_exact(float x) {
    return 0.5f * x * (1.0f + erff(x * 0.7071067811865476f));
}

// MODE 0 (PRE):  A = x_feat;          out = g_h = gelu(A@W+b); also zero g_aggr rows
// MODE 1 (MID):  A = x_feat + g_aggr; out = g_t = gelu(A@W+b); also persist A into g_x
// MODE 2 (POST): A = g_t;             out = g_x + gelu(A@W+b)  (final output)
template <int MODE>
__global__ __launch_bounds__(256, 2)
void gemm_kernel(const float* __restrict__ A0,
                 const float* __restrict__ W,
                 const float* __restrict__ bias,
                 float* __restrict__ out) {
    extern __shared__ float smem[];
    float* Xs = smem;                        // BM x XS_STRIDE
    float* Ws = smem + BM * XS_STRIDE;       // 96 x 96 (row-major: Ws[k*96+n])
    float* Bs = Ws + HID * HID;              // 96

    const int tid  = threadIdx.x;
    const int row0 = blockIdx.x * BM;

    // ---- load W (9216 floats = 2304 float4, 9 per thread, coalesced) ----
#pragma unroll
    for (int i = 0; i < 9; i++) {
        int idx4 = tid + 256 * i;
        ((float4*)Ws)[idx4] = ((const float4*)W)[idx4];
    }
    if (tid < 24) ((float4*)Bs)[tid] = ((const float4*)bias)[tid];

    // ---- load X tile (128x96 = 3072 float4, 12 per thread, coalesced) ----
#pragma unroll
    for (int i = 0; i < 12; i++) {
        int idx4 = tid + 256 * i;
        int r = idx4 / 24, c4 = idx4 % 24;
        int row = row0 + r;
        float4 v = make_float4(0.f, 0.f, 0.f, 0.f);
        if (row < N_NODES) {
            v = ((const float4*)(A0 + (size_t)row * HID))[c4];
            if (MODE == 1) {
                float4 a = ((const float4*)(g_aggr + (size_t)row * HID))[c4];
                v.x += a.x; v.y += a.y; v.z += a.z; v.w += a.w;
                ((float4*)(g_x + (size_t)row * HID))[c4] = v;  // persist residual-1
            }
        }
        float* p = &Xs[r * XS_STRIDE + c4 * 4];
        p[0] = v.x; p[1] = v.y; p[2] = v.z; p[3] = v.w;
    }
    if (MODE == 0) {
        // zero g_aggr for this block's rows (before edge kernel runs)
#pragma unroll
        for (int i = 0; i < 12; i++) {
            int idx4 = tid + 256 * i;
            int r = idx4 / 24, c4 = idx4 % 24;
            int row = row0 + r;
            if (row < N_NODES)
                ((float4*)(g_aggr + (size_t)row * HID))[c4] = make_float4(0.f, 0.f, 0.f, 0.f);
        }
    }
    __syncthreads();

    // ---- compute: 8 rows x 6 cols per thread ----
    const int tx = tid & 15;   // cols: tx + 16*j
    const int ty = tid >> 4;   // rows: ty*8 + i
    float acc[8][6];
#pragma unroll
    for (int i = 0; i < 8; i++)
#pragma unroll
        for (int j = 0; j < 6; j++) acc[i][j] = 0.f;

#pragma unroll 4
    for (int k = 0; k < HID; k++) {
        float b[6];
#pragma unroll
        for (int j = 0; j < 6; j++) b[j] = Ws[k * HID + tx + 16 * j];
#pragma unroll
        for (int i = 0; i < 8; i++) {
            float a = Xs[(ty * 8 + i) * XS_STRIDE + k];
#pragma unroll
            for (int j = 0; j < 6; j++) acc[i][j] = fmaf(a, b[j], acc[i][j]);
        }
    }

    // ---- epilogue ----
#pragma unroll
    for (int i = 0; i < 8; i++) {
        int row = row0 + ty * 8 + i;
        if (row < N_NODES) {
#pragma unroll
            for (int j = 0; j < 6; j++) {
                int col = tx + 16 * j;
                float v = acc[i][j] + Bs[col];
                float g = gelu_exact(v);
                size_t o = (size_t)row * HID + col;
                if (MODE == 2) out[o] = g_x[o] + g;
                else           out[o] = g;
            }
        }
    }
}

// Edge scatter: aggr[dst] += h[src] * bases, one float4 per thread.
// bases read is perfectly coalesced (idx IS the float4 index of bases).
__global__ __launch_bounds__(256)
void edge_kernel(const float* __restrict__ bases,
                 const int* __restrict__ src,
                 const int* __restrict__ dst) {
    int idx = blockIdx.x * 256 + threadIdx.x;            // < 19.2M, fits int
    if (idx >= N_EDGES * 24) return;
    int e = idx / 24;
    int c = idx - e * 24;
    int s = src[e];
    int d = dst[e];
    float4 b  = ((const float4*)bases)[idx];
    float4 hv = ((const float4*)(g_h + (size_t)s * HID))[c];
    float4 m  = make_float4(b.x * hv.x, b.y * hv.y, b.z * hv.z, b.w * hv.w);
    float* p = g_aggr + (size_t)d * HID + c * 4;
    asm volatile("red.global.add.v4.f32 [%0], {%1, %2, %3, %4};"
                 :: "l"(p), "f"(m.x), "f"(m.y), "f"(m.z), "f"(m.w)
                 : "memory");
}

extern "C" void kernel_launch(void* const* d_in, const int* in_sizes, int n_in,
                              void* d_out, int out_size) {
    const float* x_feat = (const float*)d_in[0];
    const float* bases  = (const float*)d_in[1];
    const float* W_pre  = (const float*)d_in[2];
    const float* b_pre  = (const float*)d_in[3];
    const float* W1     = (const float*)d_in[4];
    const float* b1     = (const float*)d_in[5];
    const float* W2     = (const float*)d_in[6];
    const float* b2     = (const float*)d_in[7];
    const int*   src    = (const int*)d_in[8];
    const int*   dst    = (const int*)d_in[9];
    float* out = (float*)d_out;

    const int smem_bytes = (BM * XS_STRIDE + HID * HID + HID) * sizeof(float);
    cudaFuncSetAttribute(gemm_kernel<0>, cudaFuncAttributeMaxDynamicSharedMemorySize, smem_bytes);
    cudaFuncSetAttribute(gemm_kernel<1>, cudaFuncAttributeMaxDynamicSharedMemorySize, smem_bytes);
    cudaFuncSetAttribute(gemm_kernel<2>, cudaFuncAttributeMaxDynamicSharedMemorySize, smem_bytes);

    float* g_h_p;    cudaGetSymbolAddress((void**)&g_h_p, g_h);
    float* g_t_p;    cudaGetSymbolAddress((void**)&g_t_p, g_t);

    const int gemm_grid = (N_NODES + BM - 1) / BM;   // 391
    const int edge_grid = (N_EDGES * 24 + 255) / 256;

    // 1) h = gelu(x_feat @ W_pre + b_pre); zero aggr
    gemm_kernel<0><<<gemm_grid, 256, smem_bytes>>>(x_feat, W_pre, b_pre, g_h_p);
    // 2) aggr[dst] += h[src] * bases
    edge_kernel<<<edge_grid, 256>>>(bases, src, dst);
    // 3) x = x_feat + aggr (persisted); t = gelu(x @ W1 + b1)
    gemm_kernel<1><<<gemm_grid, 256, smem_bytes>>>(x_feat, W1, b1, g_t_p);
    // 4) out = x + gelu(t @ W2 + b2)
    gemm_kernel<2><<<gemm_grid, 256, smem_bytes>>>(g_t_p, W2, b2, out);
}

// round 2
// speedup vs baseline: 1.1625x; 1.1625x over previous
#include <cuda_runtime.h>
#include <math.h>

#define N_NODES 50000
#define N_EDGES 800000
#define HID     96
#define BM      128
#define XS_STRIDE 97   // pad to avoid bank conflicts on LDS/STS

// Scratch (device-global: no allocation allowed)
__device__ float g_h[N_NODES * HID];     // gelu(x @ W_pre + b_pre)
__device__ float g_aggr[N_NODES * HID];  // segment_sum of h[src]*bases by dst
__device__ float g_x[N_NODES * HID];     // x_feat + aggr (residual-1 output)
__device__ float g_t[N_NODES * HID];     // gelu(x @ W1 + b1)

__device__ __forceinline__ float gelu_exact(float x) {
    return 0.5f * x * (1.0f + erff(x * 0.7071067811865476f));
}

// MODE 0 (PRE):  A = x_feat;          out = g_h = gelu(A@W+b); also zero g_aggr rows
// MODE 1 (MID):  A = x_feat + g_aggr; out = g_t = gelu(A@W+b); also persist A into g_x
// MODE 2 (POST): A = g_t;             out = g_x + gelu(A@W+b)  (final output)
template <int MODE>
__global__ __launch_bounds__(256, 2)
void gemm_kernel(const float* __restrict__ A0,
                 const float* __restrict__ W,
                 const float* __restrict__ bias,
                 float* __restrict__ out) {
    extern __shared__ float smem[];
    float* Xs = smem;                        // BM x XS_STRIDE (row-major)
    float* Ws = smem + BM * XS_STRIDE;       // 96 x 96 (row-major: Ws[k*96+n])
    float* Bs = Ws + HID * HID;              // 96

    const int tid  = threadIdx.x;
    const int row0 = blockIdx.x * BM;

    // ---- load W (9216 floats = 2304 float4, 9 per thread, coalesced) ----
#pragma unroll
    for (int i = 0; i < 9; i++) {
        int idx4 = tid + 256 * i;
        ((float4*)Ws)[idx4] = ((const float4*)W)[idx4];
    }
    if (tid < 24) ((float4*)Bs)[tid] = ((const float4*)bias)[tid];

    // ---- load X tile (128x96 = 3072 float4, 12 per thread, coalesced) ----
#pragma unroll
    for (int i = 0; i < 12; i++) {
        int idx4 = tid + 256 * i;
        int r = idx4 / 24, c4 = idx4 % 24;
        int row = row0 + r;
        float4 v = make_float4(0.f, 0.f, 0.f, 0.f);
        if (row < N_NODES) {
            v = ((const float4*)(A0 + (size_t)row * HID))[c4];
            if (MODE == 1) {
                float4 a = ((const float4*)(g_aggr + (size_t)row * HID))[c4];
                v.x += a.x; v.y += a.y; v.z += a.z; v.w += a.w;
                ((float4*)(g_x + (size_t)row * HID))[c4] = v;  // persist residual-1
            }
        }
        float* p = &Xs[r * XS_STRIDE + c4 * 4];
        p[0] = v.x; p[1] = v.y; p[2] = v.z; p[3] = v.w;
    }
    if (MODE == 0) {
        // zero g_aggr for this block's rows (before edge kernel runs)
#pragma unroll
        for (int i = 0; i < 12; i++) {
            int idx4 = tid + 256 * i;
            int r = idx4 / 24, c4 = idx4 % 24;
            int row = row0 + r;
            if (row < N_NODES)
                ((float4*)(g_aggr + (size_t)row * HID))[c4] = make_float4(0.f, 0.f, 0.f, 0.f);
        }
    }
    __syncthreads();

    // ---- compute: 8 rows x 6 cols per thread, packed f32x2 over col pairs ----
    // Thread's cols: {2*tx, 2*tx+1} + 32*j  for j = 0..2.
    // b pair comes free from LDS.64; a is duplicated into both lanes (alu pipe).
    const int tx = tid & 15;
    const int ty = tid >> 4;   // rows: ty*8 + i
    unsigned long long acc[8][3];
#pragma unroll
    for (int i = 0; i < 8; i++)
#pragma unroll
        for (int j = 0; j < 3; j++) acc[i][j] = 0ULL;

    const float* xrow = &Xs[(ty * 8) * XS_STRIDE];
    const float* wcol = &Ws[2 * tx];

#pragma unroll 4
    for (int k = 0; k < HID; k++) {
        unsigned long long b[3];
#pragma unroll
        for (int j = 0; j < 3; j++)
            b[j] = *(const unsigned long long*)(wcol + k * HID + 32 * j);
#pragma unroll
        for (int i = 0; i < 8; i++) {
            float a = xrow[i * XS_STRIDE + k];
            unsigned long long ad;
            asm("mov.b64 %0, {%1, %1};" : "=l"(ad) : "f"(a));
#pragma unroll
            for (int j = 0; j < 3; j++)
                asm("fma.rn.f32x2 %0, %1, %2, %0;"
                    : "+l"(acc[i][j]) : "l"(ad), "l"(b[j]));
        }
    }

    // ---- epilogue ----
#pragma unroll
    for (int i = 0; i < 8; i++) {
        int row = row0 + ty * 8 + i;
        if (row < N_NODES) {
#pragma unroll
            for (int j = 0; j < 3; j++) {
                float lo, hi;
                asm("mov.b64 {%0, %1}, %2;" : "=f"(lo), "=f"(hi) : "l"(acc[i][j]));
                int c0 = 2 * tx + 32 * j;
                float v0 = lo + Bs[c0];
                float v1 = hi + Bs[c0 + 1];
                float g0 = gelu_exact(v0);
                float g1 = gelu_exact(v1);
                size_t o = (size_t)row * HID + c0;
                if (MODE == 2) {
                    out[o]     = g_x[o]     + g0;
                    out[o + 1] = g_x[o + 1] + g1;
                } else {
                    out[o]     = g0;
                    out[o + 1] = g1;
                }
            }
        }
    }
}

// Edge scatter: aggr[dst] += h[src] * bases, one float4 per thread.
// bases read is perfectly coalesced (idx IS the float4 index of bases).
__global__ __launch_bounds__(256)
void edge_kernel(const float* __restrict__ bases,
                 const int* __restrict__ src,
                 const int* __restrict__ dst) {
    int idx = blockIdx.x * 256 + threadIdx.x;            // < 19.2M, fits int
    if (idx >= N_EDGES * 24) return;
    int e = idx / 24;
    int c = idx - e * 24;
    int s = src[e];
    int d = dst[e];
    float4 b  = ((const float4*)bases)[idx];
    float4 hv = ((const float4*)(g_h + (size_t)s * HID))[c];
    float4 m  = make_float4(b.x * hv.x, b.y * hv.y, b.z * hv.z, b.w * hv.w);
    float* p = g_aggr + (size_t)d * HID + c * 4;
    asm volatile("red.global.add.v4.f32 [%0], {%1, %2, %3, %4};"
                 :: "l"(p), "f"(m.x), "f"(m.y), "f"(m.z), "f"(m.w)
                 : "memory");
}

extern "C" void kernel_launch(void* const* d_in, const int* in_sizes, int n_in,
                              void* d_out, int out_size) {
    const float* x_feat = (const float*)d_in[0];
    const float* bases  = (const float*)d_in[1];
    const float* W_pre  = (const float*)d_in[2];
    const float* b_pre  = (const float*)d_in[3];
    const float* W1     = (const float*)d_in[4];
    const float* b1     = (const float*)d_in[5];
    const float* W2     = (const float*)d_in[6];
    const float* b2     = (const float*)d_in[7];
    const int*   src    = (const int*)d_in[8];
    const int*   dst    = (const int*)d_in[9];
    float* out = (float*)d_out;

    const int smem_bytes = (BM * XS_STRIDE + HID * HID + HID) * sizeof(float);
    cudaFuncSetAttribute(gemm_kernel<0>, cudaFuncAttributeMaxDynamicSharedMemorySize, smem_bytes);
    cudaFuncSetAttribute(gemm_kernel<1>, cudaFuncAttributeMaxDynamicSharedMemorySize, smem_bytes);
    cudaFuncSetAttribute(gemm_kernel<2>, cudaFuncAttributeMaxDynamicSharedMemorySize, smem_bytes);

    float* g_h_p;    cudaGetSymbolAddress((void**)&g_h_p, g_h);
    float* g_t_p;    cudaGetSymbolAddress((void**)&g_t_p, g_t);

    const int gemm_grid = (N_NODES + BM - 1) / BM;   // 391
    const int edge_grid = (N_EDGES * 24 + 255) / 256;

    // 1) h = gelu(x_feat @ W_pre + b_pre); zero aggr
    gemm_kernel<0><<<gemm_grid, 256, smem_bytes>>>(x_feat, W_pre, b_pre, g_h_p);
    // 2) aggr[dst] += h[src] * bases
    edge_kernel<<<edge_grid, 256>>>(bases, src, dst);
    // 3) x = x_feat + aggr (persisted); t = gelu(x @ W1 + b1)
    gemm_kernel<1><<<gemm_grid, 256, smem_bytes>>>(x_feat, W1, b1, g_t_p);
    // 4) out = x + gelu(t @ W2 + b2)
    gemm_kernel<2><<<gemm_grid, 256, smem_bytes>>>(g_t_p, W2, b2, out);
}